// round 12
// baseline (speedup 1.0000x reference)
#include <cuda_runtime.h>
#include <math.h>

// ---------------- problem constants ----------------
#define N_TOK 4096
#define HDIM  2048
#define NEXP  16
#define TOPK  4
#define IMOE  1408
#define ISH   5632

#define BM 128
#define BN 128
#define BKK 16
#define LDA2 130                 // ull stride for duplicated A smem (pad 2)

#define MAXROWS 18432            // 16384 assignments + up to 16*127 pad, rounded: 144*128
#define MAXTILES 144

// ---------------- scratch (device globals; no allocation allowed) ----------------
// 144*128*1408 = 25,952,256 floats = 103.8 MB ; also >= 4096*5632 = 23,068,672 (shared act)
__device__ __align__(16) float g_bufA[25952256];
__device__ __align__(16) float g_bufB[25952256];

__device__ int   g_topIdx[N_TOK * TOPK];
__device__ float g_topW[N_TOK * TOPK];
__device__ float g_sg[N_TOK];
__device__ int   g_counts[NEXP];
__device__ int   g_cursor[NEXP];
__device__ int   g_padOff[NEXP + 1];
__device__ int   g_tileExp[MAXTILES];
__device__ int   g_tok[MAXROWS];
__device__ float g_wt[MAXROWS];

// ---------------- helpers ----------------
__device__ __forceinline__ void ffma2(unsigned long long &d,
                                      unsigned long long a,
                                      unsigned long long b) {
    // packed 2xFMA fp32 (Blackwell f32x2 path) — 2x FFMA throughput
    asm("fma.rn.f32x2 %0, %1, %2, %0;" : "+l"(d) : "l"(a), "l"(b));
}

__device__ __forceinline__ unsigned long long dup2(float x) {
    unsigned long long r;
    asm("mov.b64 %0, {%1, %1};" : "=l"(r) : "f"(x));
    return r;
}

__device__ __forceinline__ float4 ld4c(const float* p, bool v) {
    if (v) return *(const float4*)p;
    return make_float4(0.f, 0.f, 0.f, 0.f);
}

// ---------------- setup kernels ----------------
__global__ void init_kernel() {
    int i = blockIdx.x * blockDim.x + threadIdx.x;   // 72*256 = 18432
    if (i < NEXP) { g_counts[i] = 0; g_cursor[i] = 0; }
    if (i < MAXROWS) g_tok[i] = -1;
}

// one block per token: 16 router logits + shared-gate logit, softmax, top-4, renorm
__global__ void router_kernel(const float* __restrict__ h,
                              const float* __restrict__ rw,
                              const float* __restrict__ sgw) {
    __shared__ float sh[HDIM];
    __shared__ float part[NEXP + 1][128];
    __shared__ float logits[NEXP + 1];

    const int n = blockIdx.x;
    const int tid = threadIdx.x;
    const float* hr = h + (long)n * HDIM;

    for (int j = tid; j < HDIM; j += 128) sh[j] = hr[j];
    __syncthreads();

    for (int e = 0; e <= NEXP; ++e) {
        const float* w = (e < NEXP) ? (rw + (long)e * HDIM) : sgw;
        float s = 0.f;
        for (int j = tid; j < HDIM; j += 128) s += sh[j] * w[j];
        part[e][tid] = s;
    }
    __syncthreads();
    if (tid <= NEXP) {
        float s = 0.f;
        for (int j = 0; j < 128; ++j) s += part[tid][j];
        logits[tid] = s;
    }
    __syncthreads();

    if (tid == 0) {
        float p[NEXP];
        float m = -1e30f;
        for (int e = 0; e < NEXP; ++e) m = fmaxf(m, logits[e]);
        float sum = 0.f;
        for (int e = 0; e < NEXP; ++e) { p[e] = expf(logits[e] - m); sum += p[e]; }
        float inv = 1.f / sum;
        for (int e = 0; e < NEXP; ++e) p[e] *= inv;

        int idx[TOPK]; float v[TOPK]; bool used[NEXP];
        for (int e = 0; e < NEXP; ++e) used[e] = false;
        float ts = 0.f;
        for (int k = 0; k < TOPK; ++k) {
            int b = 0; float bv = -1.f;
            for (int e = 0; e < NEXP; ++e)
                if (!used[e] && p[e] > bv) { bv = p[e]; b = e; }
            used[b] = true; idx[k] = b; v[k] = bv; ts += bv;
        }
        float rn = 1.f / fmaxf(ts, 1e-9f);
        for (int k = 0; k < TOPK; ++k) {
            g_topIdx[n * TOPK + k] = idx[k];
            g_topW[n * TOPK + k]   = v[k] * rn;
            atomicAdd(&g_counts[idx[k]], 1);
        }
        g_sg[n] = 1.f / (1.f + expf(-logits[NEXP]));
    }
}

__global__ void scan_kernel() {
    if (threadIdx.x == 0 && blockIdx.x == 0) {
        int off = 0;
        for (int e = 0; e < NEXP; ++e) {
            g_padOff[e] = off;
            off += ((g_counts[e] + BM - 1) / BM) * BM;
        }
        g_padOff[NEXP] = off;
        for (int t = 0; t < MAXTILES; ++t) {
            int ee = -1;
            int r = t * BM;
            if (r < off) {
                for (int x = 0; x < NEXP; ++x)
                    if (r >= g_padOff[x] && r < g_padOff[x + 1]) { ee = x; break; }
            }
            g_tileExp[t] = ee;
        }
    }
}

__global__ void scatter_kernel() {
    int id = blockIdx.x * blockDim.x + threadIdx.x;  // 64*256 = 16384
    if (id < N_TOK * TOPK) {
        int e = g_topIdx[id];
        float w = g_topW[id];
        int p = g_padOff[e] + atomicAdd(&g_cursor[e], 1);
        g_tok[p] = id >> 2;
        g_wt[p] = w;
    }
}

// bufA = silu(bufA) * bufB ; mode 1 uses device-side row count (padded routed rows)
__global__ void silu_kernel(int mode, long nFloats) {
    long n4 = ((mode == 0) ? nFloats : (long)g_padOff[NEXP] * IMOE) >> 2;
    float4* a4 = (float4*)g_bufA;
    const float4* b4 = (const float4*)g_bufB;
    long stride = (long)gridDim.x * blockDim.x;
    for (long i = (long)blockIdx.x * blockDim.x + threadIdx.x; i < n4; i += stride) {
        float4 g = a4[i];
        float4 u = b4[i];
        g.x = u.x * (g.x / (1.f + __expf(-g.x)));
        g.y = u.y * (g.y / (1.f + __expf(-g.y)));
        g.z = u.z * (g.z / (1.f + __expf(-g.z)));
        g.w = u.w * (g.w / (1.f + __expf(-g.w)));
        a4[i] = g;
    }
}

// ---------------- the GEMM ----------------
// C[M,N] = A[M,K] @ B[K,N], all row-major, dims multiples of tile sizes.
// GATHER: A row index = g_tok[globalRow] (h-row gather); inactive rows (-1) -> zeros.
// EPI 0: plain store (C row = global row)
// EPI 1: atomicAdd(C[g_tok[row]*ldc + col], g_wt[row] * acc)   (routed down -> out)
// EPI 2: store g_sg[row] * acc                                  (shared down -> out)
// aSel/cSel: 0 = g_bufA, 1 = g_bufB, 2 = external pointer
// useTiles: expert of this M-tile from g_tileExp (B += e*bStride), -1 -> exit
template<bool GATHER, int EPI>
__global__ void __launch_bounds__(256)
gemm_kernel(const float* __restrict__ Aext,
            const float* __restrict__ Bmat,
            float* __restrict__ Cext,
            int aSel, int cSel,
            int Kdim, int Ndim, int ldc,
            long bStride, int useTiles)
{
    const int mt = blockIdx.y;
    int e = 0;
    if (useTiles) { e = g_tileExp[mt]; if (e < 0) return; }

    const float* A = (aSel == 0) ? g_bufA : ((aSel == 1) ? g_bufB : Aext);
    float*       C = (cSel == 0) ? g_bufA : ((cSel == 1) ? g_bufB : Cext);
    const float* B = Bmat + (long)e * bStride;

    const int mbase = mt * BM;
    const int nbase = blockIdx.x * BN;
    const int tid = threadIdx.x;

    __shared__ __align__(16) unsigned long long As2[BKK][LDA2]; // A duplicated (x,x) pairs
    __shared__ __align__(16) float Bs[BKK][BN];

    const int arow = tid >> 2;          // 0..63
    const int acol = (tid & 3) << 2;    // 0,4,8,12
    const int brow = tid >> 5;          // 0..7
    const int bcol = (tid & 31) << 2;

    bool av0 = true, av1 = true;
    long r0, r1;
    if (GATHER) {
        int t0 = g_tok[mbase + arow];
        int t1 = g_tok[mbase + arow + 64];
        av0 = (t0 >= 0); av1 = (t1 >= 0);
        r0 = (t0 >= 0) ? t0 : 0;
        r1 = (t1 >= 0) ? t1 : 0;
    } else {
        r0 = mbase + arow;
        r1 = mbase + arow + 64;
    }
    const float* pA0 = A + r0 * (long)Kdim + acol;
    const float* pA1 = A + r1 * (long)Kdim + acol;
    const float* pB0 = B + (long)brow * Ndim + nbase + bcol;
    const float* pB1 = B + (long)(brow + 8) * Ndim + nbase + bcol;

    float4 ra0 = ld4c(pA0, av0);
    float4 ra1 = ld4c(pA1, av1);
    float4 rb0 = *(const float4*)pB0;
    float4 rb1 = *(const float4*)pB1;

    unsigned long long acc[8][4];
    #pragma unroll
    for (int i = 0; i < 8; ++i)
        #pragma unroll
        for (int j = 0; j < 4; ++j) acc[i][j] = 0ull;

    const int ty = tid >> 4;
    const int tx = tid & 15;

    for (int kt = 0; kt < Kdim; kt += BKK) {
        __syncthreads();
        As2[acol + 0][arow]      = dup2(ra0.x);
        As2[acol + 1][arow]      = dup2(ra0.y);
        As2[acol + 2][arow]      = dup2(ra0.z);
        As2[acol + 3][arow]      = dup2(ra0.w);
        As2[acol + 0][arow + 64] = dup2(ra1.x);
        As2[acol + 1][arow + 64] = dup2(ra1.y);
        As2[acol + 2][arow + 64] = dup2(ra1.z);
        As2[acol + 3][arow + 64] = dup2(ra1.w);
        *(float4*)&Bs[brow][bcol]     = rb0;
        *(float4*)&Bs[brow + 8][bcol] = rb1;
        __syncthreads();

        if (kt + BKK < Kdim) {
            pA0 += BKK; pA1 += BKK;
            pB0 += (long)BKK * Ndim; pB1 += (long)BKK * Ndim;
            ra0 = ld4c(pA0, av0);
            ra1 = ld4c(pA1, av1);
            rb0 = *(const float4*)pB0;
            rb1 = *(const float4*)pB1;
        }

        #pragma unroll
        for (int k = 0; k < BKK; ++k) {
            unsigned long long a[8], b[4];
            const unsigned long long* as = As2[k];
            #pragma unroll
            for (int i = 0; i < 4; ++i) {
                a[i]     = as[ty * 4 + i];
                a[4 + i] = as[64 + ty * 4 + i];
            }
            ulonglong2 bb0 = *(const ulonglong2*)&Bs[k][tx * 4];
            ulonglong2 bb1 = *(const ulonglong2*)&Bs[k][tx * 4 + 64];
            b[0] = bb0.x; b[1] = bb0.y; b[2] = bb1.x; b[3] = bb1.y;
            #pragma unroll
            for (int i = 0; i < 8; ++i)
                #pragma unroll
                for (int j = 0; j < 4; ++j)
                    ffma2(acc[i][j], a[i], b[j]);
        }
    }

    // epilogue — each acc[i][j] holds columns (col, col+1)
    #pragma unroll
    for (int i = 0; i < 8; ++i) {
        const int row = mbase + ty * 4 + ((i < 4) ? i : 60 + i);
        if (EPI == 1) {
            const int tok = g_tok[row];
            if (tok < 0) continue;
            const float w = g_wt[row];
            float* cr = C + (long)tok * ldc + nbase;
            #pragma unroll
            for (int j = 0; j < 4; ++j) {
                const int col = tx * 4 + ((j < 2) ? 2 * j : 60 + 2 * j);
                float lo = __uint_as_float((unsigned)(acc[i][j] & 0xFFFFFFFFull));
                float hi = __uint_as_float((unsigned)(acc[i][j] >> 32));
                atomicAdd(cr + col,     w * lo);
                atomicAdd(cr + col + 1, w * hi);
            }
        } else {
            float scale = 1.f;
            if (EPI == 2) scale = g_sg[row];
            float* cr = C + (long)row * ldc + nbase;
            #pragma unroll
            for (int j = 0; j < 4; ++j) {
                const int col = tx * 4 + ((j < 2) ? 2 * j : 60 + 2 * j);
                float lo = __uint_as_float((unsigned)(acc[i][j] & 0xFFFFFFFFull));
                float hi = __uint_as_float((unsigned)(acc[i][j] >> 32));
                if (EPI == 2) { lo *= scale; hi *= scale; }
                *(float2*)(cr + col) = make_float2(lo, hi);
            }
        }
    }
}

// ---------------- launch ----------------
extern "C" void kernel_launch(void* const* d_in, const int* in_sizes, int n_in,
                              void* d_out, int out_size) {
    (void)in_sizes; (void)n_in; (void)out_size;
    const float* h   = (const float*)d_in[0];
    const float* rw  = (const float*)d_in[1];
    const float* wg  = (const float*)d_in[2];
    const float* wu  = (const float*)d_in[3];
    const float* wd  = (const float*)d_in[4];
    const float* shg = (const float*)d_in[5];
    const float* shu = (const float*)d_in[6];
    const float* shd = (const float*)d_in[7];
    const float* sgw = (const float*)d_in[8];
    float* out = (float*)d_out;

    // routing metadata
    init_kernel<<<72, 256>>>();
    router_kernel<<<N_TOK, 128>>>(h, rw, sgw);
    scan_kernel<<<1, 1>>>();
    scatter_kernel<<<64, 256>>>();

    // --- shared expert (writes every out element => no zero-init needed) ---
    gemm_kernel<false, 0><<<dim3(ISH / BN, N_TOK / BM), 256>>>(
        h, shg, nullptr, 2, 0, HDIM, ISH, ISH, 0, 0);
    gemm_kernel<false, 0><<<dim3(ISH / BN, N_TOK / BM), 256>>>(
        h, shu, nullptr, 2, 1, HDIM, ISH, ISH, 0, 0);
    silu_kernel<<<2048, 256>>>(0, (long)N_TOK * ISH);
    gemm_kernel<false, 2><<<dim3(HDIM / BN, N_TOK / BM), 256>>>(
        nullptr, shd, out, 0, 2, ISH, HDIM, HDIM, 0, 0);

    // --- routed experts (gathered rows, per-expert padded segments) ---
    gemm_kernel<true, 0><<<dim3(IMOE / BN, MAXTILES), 256>>>(
        h, wg, nullptr, 2, 0, HDIM, IMOE, IMOE, (long)HDIM * IMOE, 1);
    gemm_kernel<true, 0><<<dim3(IMOE / BN, MAXTILES), 256>>>(
        h, wu, nullptr, 2, 1, HDIM, IMOE, IMOE, (long)HDIM * IMOE, 1);
    silu_kernel<<<2048, 256>>>(1, 0);
    gemm_kernel<false, 1><<<dim3(HDIM / BN, MAXTILES), 256>>>(
        nullptr, wd, out, 0, 2, IMOE, HDIM, HDIM, (long)IMOE * HDIM, 1);
}

// round 13
// speedup vs baseline: 1.0009x; 1.0009x over previous
#include <cuda_runtime.h>
#include <math.h>

// ---------------- problem constants ----------------
#define N_TOK 4096
#define HDIM  2048
#define NEXP  16
#define TOPK  4
#define IMOE  1408
#define ISH   5632

#define BM 128
#define BN 128
#define BKK 16
#define LDA2 130                 // ull stride for duplicated A smem (pad 2)

#define MAXROWS 18432            // 16384 assignments + up to 16*127 pad, rounded: 144*128
#define MAXTILES 144

// ---------------- scratch (device globals; no allocation allowed) ----------------
// 144*128*1408 = 25,952,256 floats = 103.8 MB ; also >= 4096*5632 = 23,068,672 (shared act)
__device__ __align__(16) float g_bufA[25952256];
__device__ __align__(16) float g_bufB[25952256];

__device__ int   g_topIdx[N_TOK * TOPK];
__device__ float g_topW[N_TOK * TOPK];
__device__ float g_sg[N_TOK];
__device__ int   g_counts[NEXP];
__device__ int   g_cursor[NEXP];
__device__ int   g_padOff[NEXP + 1];
__device__ int   g_tileExp[MAXTILES];
__device__ int   g_tok[MAXROWS];
__device__ float g_wt[MAXROWS];

// ---------------- helpers ----------------
__device__ __forceinline__ void ffma2(unsigned long long &d,
                                      unsigned long long a,
                                      unsigned long long b) {
    // packed 2xFMA fp32 (Blackwell f32x2 path) — 2x FFMA throughput
    asm("fma.rn.f32x2 %0, %1, %2, %0;" : "+l"(d) : "l"(a), "l"(b));
}

__device__ __forceinline__ unsigned long long dup2(float x) {
    unsigned long long r;
    asm("mov.b64 %0, {%1, %1};" : "=l"(r) : "f"(x));
    return r;
}

__device__ __forceinline__ float4 ld4c(const float* p, bool v) {
    if (v) return *(const float4*)p;
    return make_float4(0.f, 0.f, 0.f, 0.f);
}

// ---------------- setup kernels ----------------
__global__ void init_kernel() {
    int i = blockIdx.x * blockDim.x + threadIdx.x;   // 72*256 = 18432
    if (i < NEXP) { g_counts[i] = 0; g_cursor[i] = 0; }
    if (i < MAXROWS) g_tok[i] = -1;
}

// one block per token: 16 router logits + shared-gate logit, softmax, top-4, renorm
__global__ void router_kernel(const float* __restrict__ h,
                              const float* __restrict__ rw,
                              const float* __restrict__ sgw) {
    __shared__ float sh[HDIM];
    __shared__ float part[NEXP + 1][128];
    __shared__ float logits[NEXP + 1];

    const int n = blockIdx.x;
    const int tid = threadIdx.x;
    const float* hr = h + (long)n * HDIM;

    for (int j = tid; j < HDIM; j += 128) sh[j] = hr[j];
    __syncthreads();

    for (int e = 0; e <= NEXP; ++e) {
        const float* w = (e < NEXP) ? (rw + (long)e * HDIM) : sgw;
        float s = 0.f;
        for (int j = tid; j < HDIM; j += 128) s += sh[j] * w[j];
        part[e][tid] = s;
    }
    __syncthreads();
    if (tid <= NEXP) {
        float s = 0.f;
        for (int j = 0; j < 128; ++j) s += part[tid][j];
        logits[tid] = s;
    }
    __syncthreads();

    if (tid == 0) {
        float p[NEXP];
        float m = -1e30f;
        for (int e = 0; e < NEXP; ++e) m = fmaxf(m, logits[e]);
        float sum = 0.f;
        for (int e = 0; e < NEXP; ++e) { p[e] = expf(logits[e] - m); sum += p[e]; }
        float inv = 1.f / sum;
        for (int e = 0; e < NEXP; ++e) p[e] *= inv;

        int idx[TOPK]; float v[TOPK]; bool used[NEXP];
        for (int e = 0; e < NEXP; ++e) used[e] = false;
        float ts = 0.f;
        for (int k = 0; k < TOPK; ++k) {
            int b = 0; float bv = -1.f;
            for (int e = 0; e < NEXP; ++e)
                if (!used[e] && p[e] > bv) { bv = p[e]; b = e; }
            used[b] = true; idx[k] = b; v[k] = bv; ts += bv;
        }
        float rn = 1.f / fmaxf(ts, 1e-9f);
        for (int k = 0; k < TOPK; ++k) {
            g_topIdx[n * TOPK + k] = idx[k];
            g_topW[n * TOPK + k]   = v[k] * rn;
            atomicAdd(&g_counts[idx[k]], 1);
        }
        g_sg[n] = 1.f / (1.f + expf(-logits[NEXP]));
    }
}

__global__ void scan_kernel() {
    if (threadIdx.x == 0 && blockIdx.x == 0) {
        int off = 0;
        for (int e = 0; e < NEXP; ++e) {
            g_padOff[e] = off;
            off += ((g_counts[e] + BM - 1) / BM) * BM;
        }
        g_padOff[NEXP] = off;
        for (int t = 0; t < MAXTILES; ++t) {
            int ee = -1;
            int r = t * BM;
            if (r < off) {
                for (int x = 0; x < NEXP; ++x)
                    if (r >= g_padOff[x] && r < g_padOff[x + 1]) { ee = x; break; }
            }
            g_tileExp[t] = ee;
        }
    }
}

__global__ void scatter_kernel() {
    int id = blockIdx.x * blockDim.x + threadIdx.x;  // 64*256 = 16384
    if (id < N_TOK * TOPK) {
        int e = g_topIdx[id];
        float w = g_topW[id];
        int p = g_padOff[e] + atomicAdd(&g_cursor[e], 1);
        g_tok[p] = id >> 2;
        g_wt[p] = w;
    }
}

// bufA = silu(bufA) * bufB ; mode 1 uses device-side row count (padded routed rows)
__global__ void silu_kernel(int mode, long nFloats) {
    long n4 = ((mode == 0) ? nFloats : (long)g_padOff[NEXP] * IMOE) >> 2;
    float4* a4 = (float4*)g_bufA;
    const float4* b4 = (const float4*)g_bufB;
    long stride = (long)gridDim.x * blockDim.x;
    for (long i = (long)blockIdx.x * blockDim.x + threadIdx.x; i < n4; i += stride) {
        float4 g = a4[i];
        float4 u = b4[i];
        g.x = u.x * (g.x / (1.f + __expf(-g.x)));
        g.y = u.y * (g.y / (1.f + __expf(-g.y)));
        g.z = u.z * (g.z / (1.f + __expf(-g.z)));
        g.w = u.w * (g.w / (1.f + __expf(-g.w)));
        a4[i] = g;
    }
}

// ---------------- the GEMM ----------------
// C[M,N] = A[M,K] @ B[K,N], all row-major, dims multiples of tile sizes.
// GATHER: A row index = g_tok[globalRow] (h-row gather); inactive rows (-1) -> zeros.
// EPI 0: plain store (C row = global row)
// EPI 1: atomicAdd(C[g_tok[row]*ldc + col], g_wt[row] * acc)   (routed down -> out)
// EPI 2: store g_sg[row] * acc                                  (shared down -> out)
// aSel/cSel: 0 = g_bufA, 1 = g_bufB, 2 = external pointer
// useTiles: expert of this M-tile from g_tileExp (B += e*bStride), -1 -> exit
template<bool GATHER, int EPI>
__global__ void __launch_bounds__(256)
gemm_kernel(const float* __restrict__ Aext,
            const float* __restrict__ Bmat,
            float* __restrict__ Cext,
            int aSel, int cSel,
            int Kdim, int Ndim, int ldc,
            long bStride, int useTiles)
{
    const int mt = blockIdx.y;
    int e = 0;
    if (useTiles) { e = g_tileExp[mt]; if (e < 0) return; }

    const float* A = (aSel == 0) ? g_bufA : ((aSel == 1) ? g_bufB : Aext);
    float*       C = (cSel == 0) ? g_bufA : ((cSel == 1) ? g_bufB : Cext);
    const float* B = Bmat + (long)e * bStride;

    const int mbase = mt * BM;
    const int nbase = blockIdx.x * BN;
    const int tid = threadIdx.x;

    __shared__ __align__(16) unsigned long long As2[BKK][LDA2]; // A duplicated (x,x) pairs
    __shared__ __align__(16) float Bs[BKK][BN];

    const int arow = tid >> 2;          // 0..63
    const int acol = (tid & 3) << 2;    // 0,4,8,12
    const int brow = tid >> 5;          // 0..7
    const int bcol = (tid & 31) << 2;

    bool av0 = true, av1 = true;
    long r0, r1;
    if (GATHER) {
        int t0 = g_tok[mbase + arow];
        int t1 = g_tok[mbase + arow + 64];
        av0 = (t0 >= 0); av1 = (t1 >= 0);
        r0 = (t0 >= 0) ? t0 : 0;
        r1 = (t1 >= 0) ? t1 : 0;
    } else {
        r0 = mbase + arow;
        r1 = mbase + arow + 64;
    }
    const float* pA0 = A + r0 * (long)Kdim + acol;
    const float* pA1 = A + r1 * (long)Kdim + acol;
    const float* pB0 = B + (long)brow * Ndim + nbase + bcol;
    const float* pB1 = B + (long)(brow + 8) * Ndim + nbase + bcol;

    float4 ra0 = ld4c(pA0, av0);
    float4 ra1 = ld4c(pA1, av1);
    float4 rb0 = *(const float4*)pB0;
    float4 rb1 = *(const float4*)pB1;

    unsigned long long acc[8][4];
    #pragma unroll
    for (int i = 0; i < 8; ++i)
        #pragma unroll
        for (int j = 0; j < 4; ++j) acc[i][j] = 0ull;

    const int ty = tid >> 4;
    const int tx = tid & 15;

    for (int kt = 0; kt < Kdim; kt += BKK) {
        __syncthreads();
        As2[acol + 0][arow]      = dup2(ra0.x);
        As2[acol + 1][arow]      = dup2(ra0.y);
        As2[acol + 2][arow]      = dup2(ra0.z);
        As2[acol + 3][arow]      = dup2(ra0.w);
        As2[acol + 0][arow + 64] = dup2(ra1.x);
        As2[acol + 1][arow + 64] = dup2(ra1.y);
        As2[acol + 2][arow + 64] = dup2(ra1.z);
        As2[acol + 3][arow + 64] = dup2(ra1.w);
        *(float4*)&Bs[brow][bcol]     = rb0;
        *(float4*)&Bs[brow + 8][bcol] = rb1;
        __syncthreads();

        if (kt + BKK < Kdim) {
            pA0 += BKK; pA1 += BKK;
            pB0 += (long)BKK * Ndim; pB1 += (long)BKK * Ndim;
            ra0 = ld4c(pA0, av0);
            ra1 = ld4c(pA1, av1);
            rb0 = *(const float4*)pB0;
            rb1 = *(const float4*)pB1;
        }

        #pragma unroll
        for (int k = 0; k < BKK; ++k) {
            unsigned long long a[8], b[4];
            const unsigned long long* as = As2[k];
            #pragma unroll
            for (int i = 0; i < 4; ++i) {
                a[i]     = as[ty * 4 + i];
                a[4 + i] = as[64 + ty * 4 + i];
            }
            ulonglong2 bb0 = *(const ulonglong2*)&Bs[k][tx * 4];
            ulonglong2 bb1 = *(const ulonglong2*)&Bs[k][tx * 4 + 64];
            b[0] = bb0.x; b[1] = bb0.y; b[2] = bb1.x; b[3] = bb1.y;
            #pragma unroll
            for (int i = 0; i < 8; ++i)
                #pragma unroll
                for (int j = 0; j < 4; ++j)
                    ffma2(acc[i][j], a[i], b[j]);
        }
    }

    // epilogue — each acc[i][j] holds columns (col, col+1)
    #pragma unroll
    for (int i = 0; i < 8; ++i) {
        const int row = mbase + ty * 4 + ((i < 4) ? i : 60 + i);
        if (EPI == 1) {
            const int tok = g_tok[row];
            if (tok < 0) continue;
            const float w = g_wt[row];
            float* cr = C + (long)tok * ldc + nbase;
            #pragma unroll
            for (int j = 0; j < 4; ++j) {
                const int col = tx * 4 + ((j < 2) ? 2 * j : 60 + 2 * j);
                float lo = __uint_as_float((unsigned)(acc[i][j] & 0xFFFFFFFFull));
                float hi = __uint_as_float((unsigned)(acc[i][j] >> 32));
                atomicAdd(cr + col,     w * lo);
                atomicAdd(cr + col + 1, w * hi);
            }
        } else {
            float scale = 1.f;
            if (EPI == 2) scale = g_sg[row];
            float* cr = C + (long)row * ldc + nbase;
            #pragma unroll
            for (int j = 0; j < 4; ++j) {
                const int col = tx * 4 + ((j < 2) ? 2 * j : 60 + 2 * j);
                float lo = __uint_as_float((unsigned)(acc[i][j] & 0xFFFFFFFFull));
                float hi = __uint_as_float((unsigned)(acc[i][j] >> 32));
                if (EPI == 2) { lo *= scale; hi *= scale; }
                *(float2*)(cr + col) = make_float2(lo, hi);
            }
        }
    }
}

// ---------------- launch ----------------
extern "C" void kernel_launch(void* const* d_in, const int* in_sizes, int n_in,
                              void* d_out, int out_size) {
    (void)in_sizes; (void)n_in; (void)out_size;
    const float* h   = (const float*)d_in[0];
    const float* rw  = (const float*)d_in[1];
    const float* wg  = (const float*)d_in[2];
    const float* wu  = (const float*)d_in[3];
    const float* wd  = (const float*)d_in[4];
    const float* shg = (const float*)d_in[5];
    const float* shu = (const float*)d_in[6];
    const float* shd = (const float*)d_in[7];
    const float* sgw = (const float*)d_in[8];
    float* out = (float*)d_out;

    // routing metadata
    init_kernel<<<72, 256>>>();
    router_kernel<<<N_TOK, 128>>>(h, rw, sgw);
    scan_kernel<<<1, 1>>>();
    scatter_kernel<<<64, 256>>>();

    // --- shared expert (writes every out element => no zero-init needed) ---
    gemm_kernel<false, 0><<<dim3(ISH / BN, N_TOK / BM), 256>>>(
        h, shg, nullptr, 2, 0, HDIM, ISH, ISH, 0, 0);
    gemm_kernel<false, 0><<<dim3(ISH / BN, N_TOK / BM), 256>>>(
        h, shu, nullptr, 2, 1, HDIM, ISH, ISH, 0, 0);
    silu_kernel<<<2048, 256>>>(0, (long)N_TOK * ISH);
    gemm_kernel<false, 2><<<dim3(HDIM / BN, N_TOK / BM), 256>>>(
        nullptr, shd, out, 0, 2, ISH, HDIM, HDIM, 0, 0);

    // --- routed experts (gathered rows, per-expert padded segments) ---
    gemm_kernel<true, 0><<<dim3(IMOE / BN, MAXTILES), 256>>>(
        h, wg, nullptr, 2, 0, HDIM, IMOE, IMOE, (long)HDIM * IMOE, 1);
    gemm_kernel<true, 0><<<dim3(IMOE / BN, MAXTILES), 256>>>(
        h, wu, nullptr, 2, 1, HDIM, IMOE, IMOE, (long)HDIM * IMOE, 1);
    silu_kernel<<<2048, 256>>>(1, 0);
    gemm_kernel<false, 1><<<dim3(HDIM / BN, MAXTILES), 256>>>(
        nullptr, wd, out, 0, 2, IMOE, HDIM, HDIM, (long)IMOE * HDIM, 1);
}